// round 14
// baseline (speedup 1.0000x reference)
#include <cuda_runtime.h>
#include <cuda_fp16.h>
#include <cstdint>

#define A_N 4
#define E_N 128
#define S_N 3072
#define NPIX (512 * 256)              // 131072
#define THREADS 1024
#define RPT 4                         // pixels per thread (strided, reg acc)
#define TILE_PX (THREADS * RPT)       // 4096
#define NTILE (NPIX / TILE_PX)        // 32
#define NGROUP 4                      // split-K groups
#define EPC (E_N / NGROUP)            // 32 elements per CTA
#define NPHASE EPC
#define GRID (NTILE * NGROUP)         // 128
#define R4 (S_N / 4)                  // 768 uint4 per packed row
#define BUF_U4 (A_N * R4)             // 3072 uint4 per buffer (48KB)
#define NBUF 4
#define SMEM_BYTES (NBUF * BUF_U4 * 16)   // 196608

#define ZERO_BLOCKS 512               // zero-fill portion of init grid
#define PACK_BLOCKS (A_N * E_N * R4 / 256)   // 1536
#define INIT_GRID (ZERO_BLOCKS + PACK_BLOCKS)

// Pre-packed rf: [A][E][S] half2 pairs, entry i = (rf[i], rf[i+1])  (6MB)
__device__ half2 g_packed[A_N * E_N * S_N];

__device__ __forceinline__ void cp_async16(void* smem_ptr, const void* gptr) {
    unsigned s = (unsigned)__cvta_generic_to_shared(smem_ptr);
    asm volatile("cp.async.cg.shared.global [%0], [%1], 16;\n" :: "r"(s), "l"(gptr));
}

// ---- fused init: zero d_out (blocks 0..511) + pack rf (blocks 512..2047) ----
__global__ void __launch_bounds__(256)
das_init(const float* __restrict__ rf, float4* __restrict__ out4)
{
    int b = blockIdx.x;
    if (b < ZERO_BLOCKS) {
        out4[b * 256 + threadIdx.x] = make_float4(0.f, 0.f, 0.f, 0.f);
        return;
    }
    int c = (b - ZERO_BLOCKS) * 256 + threadIdx.x;  // uint4 idx 0..A*E*R4-1
    int row = c / R4;                                // a*E_N + e
    int col = c - row * R4;
    const float* grow = rf + (size_t)row * S_N;
    float4 v  = ((const float4*)grow)[col];
    float  s4 = grow[min(col * 4 + 4, S_N - 1)];
    half2 q0 = __floats2half2_rn(v.x, v.y);
    half2 q1 = __floats2half2_rn(v.y, v.z);
    half2 q2 = __floats2half2_rn(v.z, v.w);
    half2 q3 = __floats2half2_rn(v.w, s4);
    uint4 pk;
    pk.x = *(unsigned*)&q0; pk.y = *(unsigned*)&q1;
    pk.z = *(unsigned*)&q2; pk.w = *(unsigned*)&q3;
    ((uint4*)g_packed)[c] = pk;
}

__global__ void __launch_bounds__(THREADS, 1)
das_main(const float* __restrict__ d_tx, const float* __restrict__ d_rx,
         const float* __restrict__ apod, const float* __restrict__ t0,
         float* __restrict__ out)
{
    extern __shared__ half2 smh[];        // 4 buffers x 4 rows x S_N half2
    uint4* sm4 = (uint4*)smh;
    const uint4* gp4 = (const uint4*)g_packed;

    const int tid   = threadIdx.x;
    const int group = blockIdx.x & (NGROUP - 1);
    const int tile  = blockIdx.x >> 2;
    const int ebase = group * EPC;
    const int p0    = tile * TILE_PX + tid;     // strided pixels

    auto stage = [&](int buf, int e) {
#pragma unroll
        for (int k = 0; k < BUF_U4 / THREADS; k++) {   // 3 chunks/thread
            int c   = tid + k * THREADS;
            int a   = c / R4;
            int col = c - a * R4;
            cp_async16(&sm4[buf * BUF_U4 + c],
                       &gp4[((size_t)a * E_N + e) * R4 + col]);
        }
        asm volatile("cp.async.commit_group;\n" ::);
    };

    float dtx[A_N][RPT];
    float acc[A_N][RPT];
#pragma unroll
    for (int a = 0; a < A_N; a++) {
        float t0a = t0[a];
#pragma unroll
        for (int r = 0; r < RPT; r++) {
            dtx[a][r] = d_tx[(size_t)a * NPIX + p0 + r * THREADS] - t0a;
            acc[a][r] = 0.0f;
        }
    }

    stage(0, ebase);
    stage(1, ebase + 1);

    for (int ph = 0; ph < NPHASE; ph++) {
        // 1) keep rf pipeline 2 deep
        if (ph + 2 < NPHASE)
            stage((ph + 2) & 3, ebase + ph + 2);

        // 2) issue THIS phase's scalar LDGs before the wait+barrier —
        //    their ~600cyc latency hides under the cp.async wait and bar
        const int e = ebase + ph;
        float drx[RPT], ap[RPT];
#pragma unroll
        for (int r = 0; r < RPT; r++) {
            size_t off = (size_t)e * NPIX + p0 + r * THREADS;
            drx[r] = d_rx[off];
            ap[r]  = apod[off];
        }

        // 3) wait for buffer ph, make visible
        if (ph + 2 < NPHASE) {
            asm volatile("cp.async.wait_group 2;\n" ::);
        } else if (ph + 2 == NPHASE) {
            asm volatile("cp.async.wait_group 1;\n" ::);
        } else {
            asm volatile("cp.async.wait_group 0;\n" ::);
        }
        __syncthreads();

        const half2* bufp = smh + (size_t)(ph & 3) * A_N * S_N;

#pragma unroll
        for (int r = 0; r < RPT; r++) {
#pragma unroll
            for (int a = 0; a < A_N; a++) {
                const half2* row = bufp + a * S_N;
                float delay = dtx[a][r] + drx[r];
                // delay guaranteed in [0, 3070): trunc == floor, no clamp
                int   i0 = (int)delay;
                float w  = delay - (float)i0;
                half2 pr = row[i0];               // 1 LDS.32: (rf[i0], rf[i0+1])
                float v0 = __low2float(pr);
                float v1 = __high2float(pr);
                float s  = fmaf(w, v1 - v0, v0);
                acc[a][r] = fmaf(s, ap[r], acc[a][r]);
            }
        }
    }

    // Atomic epilogue: 4 groups accumulate directly into out
#pragma unroll
    for (int a = 0; a < A_N; a++)
#pragma unroll
        for (int r = 0; r < RPT; r++)
            atomicAdd(&out[(size_t)a * NPIX + p0 + r * THREADS], acc[a][r]);
}

extern "C" void kernel_launch(void* const* d_in, const int* in_sizes, int n_in,
                              void* d_out, int out_size)
{
    const float* d_tx = (const float*)d_in[0];   // [A, NZ, NX]
    const float* d_rx = (const float*)d_in[1];   // [E, NZ, NX]
    const float* apod = (const float*)d_in[2];   // [E, NZ, NX]
    const float* rf   = (const float*)d_in[3];   // [A, E, S]
    const float* t0   = (const float*)d_in[4];   // [A]
    float* out = (float*)d_out;                  // [A, NZ, NX]

    cudaFuncSetAttribute(das_main,
                         cudaFuncAttributeMaxDynamicSharedMemorySize,
                         SMEM_BYTES);

    das_init<<<INIT_GRID, 256>>>(rf, (float4*)out);
    das_main<<<GRID, THREADS, SMEM_BYTES>>>(d_tx, d_rx, apod, t0, out);
}

// round 15
// speedup vs baseline: 1.1405x; 1.1405x over previous
#include <cuda_runtime.h>
#include <cuda_fp16.h>
#include <cstdint>

#define A_N 4
#define E_N 128
#define S_N 3072
#define NPIX (512 * 256)              // 131072
#define THREADS 1024
#define RPT 4                         // pixels per thread (strided, reg acc)
#define TILE_PX (THREADS * RPT)       // 4096
#define NTILE (NPIX / TILE_PX)        // 32
#define NGROUP 4                      // split-K groups
#define EPC (E_N / NGROUP)            // 32 elements per CTA
#define NPHASE EPC
#define GRID (NTILE * NGROUP)         // 128
#define R4 (S_N / 4)                  // 768 uint4 per packed row
#define BUF_U4 (A_N * R4)             // 3072 uint4 per buffer (48KB)
#define NBUF 4
#define SMEM_BYTES (NBUF * BUF_U4 * 16)   // 196608

#define ZERO_BLOCKS 512               // zero-fill portion of init grid
#define PACK_BLOCKS (A_N * E_N * R4 / 256)   // 1536
#define INIT_GRID (ZERO_BLOCKS + PACK_BLOCKS)

// Pre-packed rf: [A][E][S] half2, entry i = (rf[i], rf[i+1]-rf[i])  (6MB)
__device__ half2 g_packed[A_N * E_N * S_N];

__device__ __forceinline__ void cp_async16(void* smem_ptr, const void* gptr) {
    unsigned s = (unsigned)__cvta_generic_to_shared(smem_ptr);
    asm volatile("cp.async.cg.shared.global [%0], [%1], 16;\n" :: "r"(s), "l"(gptr));
}

// ---- fused init: zero d_out + pack rf as (value, forward-difference) ----
__global__ void __launch_bounds__(256)
das_init(const float* __restrict__ rf, float4* __restrict__ out4)
{
    int b = blockIdx.x;
    if (b < ZERO_BLOCKS) {
        out4[b * 256 + threadIdx.x] = make_float4(0.f, 0.f, 0.f, 0.f);
        return;
    }
    int c = (b - ZERO_BLOCKS) * 256 + threadIdx.x;  // uint4 idx 0..A*E*R4-1
    int row = c / R4;                                // a*E_N + e
    int col = c - row * R4;
    const float* grow = rf + (size_t)row * S_N;
    float4 v  = ((const float4*)grow)[col];
    float  s4 = grow[min(col * 4 + 4, S_N - 1)];
    // (v0, dv) pairs: lerp = v0 + w*dv
    half2 q0 = __floats2half2_rn(v.x, v.y - v.x);
    half2 q1 = __floats2half2_rn(v.y, v.z - v.y);
    half2 q2 = __floats2half2_rn(v.z, v.w - v.z);
    half2 q3 = __floats2half2_rn(v.w, s4  - v.w);
    uint4 pk;
    pk.x = *(unsigned*)&q0; pk.y = *(unsigned*)&q1;
    pk.z = *(unsigned*)&q2; pk.w = *(unsigned*)&q3;
    ((uint4*)g_packed)[c] = pk;
}

__global__ void __launch_bounds__(THREADS, 1)
das_main(const float* __restrict__ d_tx, const float* __restrict__ d_rx,
         const float* __restrict__ apod, const float* __restrict__ t0,
         float* __restrict__ out)
{
    extern __shared__ half2 smh[];        // 4 buffers x 4 rows x S_N half2
    uint4* sm4 = (uint4*)smh;
    const uint4* gp4 = (const uint4*)g_packed;

    const int tid   = threadIdx.x;
    const int group = blockIdx.x & (NGROUP - 1);
    const int tile  = blockIdx.x >> 2;
    const int ebase = group * EPC;
    const int p0    = tile * TILE_PX + tid;     // strided pixels

    auto stage = [&](int buf, int e) {
#pragma unroll
        for (int k = 0; k < BUF_U4 / THREADS; k++) {   // 3 chunks/thread
            int c   = tid + k * THREADS;
            int a   = c / R4;
            int col = c - a * R4;
            cp_async16(&sm4[buf * BUF_U4 + c],
                       &gp4[((size_t)a * E_N + e) * R4 + col]);
        }
        asm volatile("cp.async.commit_group;\n" ::);
    };

    float dtx[A_N][RPT];
    float acc[A_N][RPT];
#pragma unroll
    for (int a = 0; a < A_N; a++) {
        float t0a = t0[a];
#pragma unroll
        for (int r = 0; r < RPT; r++) {
            dtx[a][r] = d_tx[(size_t)a * NPIX + p0 + r * THREADS] - t0a;
            acc[a][r] = 0.0f;
        }
    }

    stage(0, ebase);
    stage(1, ebase + 1);

    for (int ph = 0; ph < NPHASE; ph++) {
        if (ph + 2 < NPHASE) {
            stage((ph + 2) & 3, ebase + ph + 2);
            asm volatile("cp.async.wait_group 2;\n" ::);
        } else if (ph + 2 == NPHASE) {
            asm volatile("cp.async.wait_group 1;\n" ::);
        } else {
            asm volatile("cp.async.wait_group 0;\n" ::);
        }
        __syncthreads();

        const int e = ebase + ph;
        const half2* bufp = smh + (size_t)(ph & 3) * A_N * S_N;

        // Scalar loads AFTER the barrier (R13 ordering — proven fastest)
        float drx[RPT], ap[RPT];
#pragma unroll
        for (int r = 0; r < RPT; r++) {
            size_t off = (size_t)e * NPIX + p0 + r * THREADS;
            drx[r] = d_rx[off];
            ap[r]  = apod[off];
        }

#pragma unroll
        for (int r = 0; r < RPT; r++) {
#pragma unroll
            for (int a = 0; a < A_N; a++) {
                const half2* row = bufp + a * S_N;
                float delay = dtx[a][r] + drx[r];
                float f  = floorf(delay);
                float w  = delay - f;
                int   i0 = (int)f;        // in-range by data (validated fp32 rounds)
                half2 pr = row[i0];       // 1 LDS.32: (v0, dv)
                float v0 = __low2float(pr);
                float dv = __high2float(pr);
                float s  = fmaf(w, dv, v0);           // v0 + w*(v1-v0)
                acc[a][r] = fmaf(s, ap[r], acc[a][r]);
            }
        }
    }

    // Atomic epilogue: 4 groups accumulate directly into out
#pragma unroll
    for (int a = 0; a < A_N; a++)
#pragma unroll
        for (int r = 0; r < RPT; r++)
            atomicAdd(&out[(size_t)a * NPIX + p0 + r * THREADS], acc[a][r]);
}

extern "C" void kernel_launch(void* const* d_in, const int* in_sizes, int n_in,
                              void* d_out, int out_size)
{
    const float* d_tx = (const float*)d_in[0];   // [A, NZ, NX]
    const float* d_rx = (const float*)d_in[1];   // [E, NZ, NX]
    const float* apod = (const float*)d_in[2];   // [E, NZ, NX]
    const float* rf   = (const float*)d_in[3];   // [A, E, S]
    const float* t0   = (const float*)d_in[4];   // [A]
    float* out = (float*)d_out;                  // [A, NZ, NX]

    cudaFuncSetAttribute(das_main,
                         cudaFuncAttributeMaxDynamicSharedMemorySize,
                         SMEM_BYTES);

    das_init<<<INIT_GRID, 256>>>(rf, (float4*)out);
    das_main<<<GRID, THREADS, SMEM_BYTES>>>(d_tx, d_rx, apod, t0, out);
}

// round 16
// speedup vs baseline: 1.1867x; 1.0405x over previous
#include <cuda_runtime.h>
#include <cuda_fp16.h>
#include <cstdint>

#define A_N 4
#define E_N 128
#define S_N 3072
#define NPIX (512 * 256)              // 131072
#define THREADS 1024
#define RPT 4                         // pixels per thread (strided, reg acc)
#define TILE_PX (THREADS * RPT)       // 4096
#define NTILE (NPIX / TILE_PX)        // 32
#define NGROUP 4                      // split-K groups
#define EPC (E_N / NGROUP)            // 32 elements per CTA
#define NPHASE EPC
#define GRID (NTILE * NGROUP)         // 128
#define R4 (S_N / 4)                  // 768 uint4 per packed rf row
#define RF_U4 (A_N * R4)              // 3072 uint4 rf per buffer (48KB)
#define SC_U4 (TILE_PX / 4)           // 1024 uint4 per scalar array (16KB)
#define BUF_U4 (RF_U4 + 2 * SC_U4)    // 5120 uint4 = 80KB per buffer
#define NBUF 2
#define SMEM_BYTES (NBUF * BUF_U4 * 16)   // 163840

#define ZERO_BLOCKS 512
#define PACK_BLOCKS (A_N * E_N * R4 / 256)   // 1536
#define INIT_GRID (ZERO_BLOCKS + PACK_BLOCKS)

// Pre-packed rf: [A][E][S] half2, entry i = (rf[i], rf[i+1]-rf[i])  (6MB)
__device__ half2 g_packed[A_N * E_N * S_N];

__device__ __forceinline__ void cp_async16(void* smem_ptr, const void* gptr) {
    unsigned s = (unsigned)__cvta_generic_to_shared(smem_ptr);
    asm volatile("cp.async.cg.shared.global [%0], [%1], 16;\n" :: "r"(s), "l"(gptr));
}

// ---- fused init: zero d_out + pack rf as (value, forward-difference) ----
__global__ void __launch_bounds__(256)
das_init(const float* __restrict__ rf, float4* __restrict__ out4)
{
    int b = blockIdx.x;
    if (b < ZERO_BLOCKS) {
        out4[b * 256 + threadIdx.x] = make_float4(0.f, 0.f, 0.f, 0.f);
        return;
    }
    int c = (b - ZERO_BLOCKS) * 256 + threadIdx.x;  // uint4 idx 0..A*E*R4-1
    int row = c / R4;                                // a*E_N + e
    int col = c - row * R4;
    const float* grow = rf + (size_t)row * S_N;
    float4 v  = ((const float4*)grow)[col];
    float  s4 = grow[min(col * 4 + 4, S_N - 1)];
    half2 q0 = __floats2half2_rn(v.x, v.y - v.x);
    half2 q1 = __floats2half2_rn(v.y, v.z - v.y);
    half2 q2 = __floats2half2_rn(v.z, v.w - v.z);
    half2 q3 = __floats2half2_rn(v.w, s4  - v.w);
    uint4 pk;
    pk.x = *(unsigned*)&q0; pk.y = *(unsigned*)&q1;
    pk.z = *(unsigned*)&q2; pk.w = *(unsigned*)&q3;
    ((uint4*)g_packed)[c] = pk;
}

__global__ void __launch_bounds__(THREADS, 1)
das_main(const float* __restrict__ d_tx, const float* __restrict__ d_rx,
         const float* __restrict__ apod, const float* __restrict__ t0,
         float* __restrict__ out)
{
    // buffer layout (uint4): [0,3072) rf | [3072,4096) drx | [4096,5120) apod
    extern __shared__ uint4 sm4[];
    const uint4* gp4 = (const uint4*)g_packed;

    const int tid   = threadIdx.x;
    const int group = blockIdx.x & (NGROUP - 1);
    const int tile  = blockIdx.x >> 2;
    const int ebase = group * EPC;
    const int pbase = tile * TILE_PX;
    const int p0    = pbase + tid;               // strided pixels

    // stage rf rows + this element's scalar tiles into buffer `buf`
    auto stage = [&](int buf, int e) {
        uint4* dst = sm4 + buf * BUF_U4;
#pragma unroll
        for (int k = 0; k < RF_U4 / THREADS; k++) {    // 3 rf chunks/thread
            int c   = tid + k * THREADS;
            int a   = c / R4;
            int col = c - a * R4;
            cp_async16(&dst[c], &gp4[((size_t)a * E_N + e) * R4 + col]);
        }
        const uint4* gdrx = (const uint4*)(d_rx + (size_t)e * NPIX + pbase);
        const uint4* gap  = (const uint4*)(apod + (size_t)e * NPIX + pbase);
        cp_async16(&dst[RF_U4 + tid],         &gdrx[tid]);   // 16KB drx
        cp_async16(&dst[RF_U4 + SC_U4 + tid], &gap[tid]);    // 16KB apod
        asm volatile("cp.async.commit_group;\n" ::);
    };

    float dtx[A_N][RPT];
    float acc[A_N][RPT];
#pragma unroll
    for (int a = 0; a < A_N; a++) {
        float t0a = t0[a];
#pragma unroll
        for (int r = 0; r < RPT; r++) {
            dtx[a][r] = d_tx[(size_t)a * NPIX + p0 + r * THREADS] - t0a;
            acc[a][r] = 0.0f;
        }
    }

    stage(0, ebase);                         // prologue

    for (int ph = 0; ph < NPHASE; ph++) {
        // Prefetch next phase into the other buffer (safe: its last readers
        // finished before the trailing barrier of phase ph-1).
        if (ph + 1 < NPHASE) {
            stage((ph + 1) & 1, ebase + ph + 1);
            asm volatile("cp.async.wait_group 1;\n" ::);  // buf ph complete
        } else {
            asm volatile("cp.async.wait_group 0;\n" ::);
        }
        __syncthreads();                     // buf ph visible

        const uint4* bufb = sm4 + (ph & 1) * BUF_U4;
        const half2* rfp  = (const half2*)bufb;
        const float* sdrx = (const float*)(bufb + RF_U4);
        const float* sap  = (const float*)(bufb + RF_U4 + SC_U4);

#pragma unroll
        for (int r = 0; r < RPT; r++) {
            // conflict-free coalesced LDS (29cyc) instead of bursty LDG
            float drx = sdrx[tid + r * THREADS];
            float ap  = sap [tid + r * THREADS];
#pragma unroll
            for (int a = 0; a < A_N; a++) {
                const half2* row = rfp + a * S_N;
                float delay = dtx[a][r] + drx;
                float f  = floorf(delay);
                float w  = delay - f;
                int   i0 = (int)f;           // in-range by data
                half2 pr = row[i0];          // 1 LDS.32: (v0, dv)
                float v0 = __low2float(pr);
                float dv = __high2float(pr);
                float s  = fmaf(w, dv, v0);
                acc[a][r] = fmaf(s, ap, acc[a][r]);
            }
        }
        __syncthreads();                     // reads done before buf reuse
    }

    // Atomic epilogue: 4 groups accumulate directly into out
#pragma unroll
    for (int a = 0; a < A_N; a++)
#pragma unroll
        for (int r = 0; r < RPT; r++)
            atomicAdd(&out[(size_t)a * NPIX + p0 + r * THREADS], acc[a][r]);
}

extern "C" void kernel_launch(void* const* d_in, const int* in_sizes, int n_in,
                              void* d_out, int out_size)
{
    const float* d_tx = (const float*)d_in[0];   // [A, NZ, NX]
    const float* d_rx = (const float*)d_in[1];   // [E, NZ, NX]
    const float* apod = (const float*)d_in[2];   // [E, NZ, NX]
    const float* rf   = (const float*)d_in[3];   // [A, E, S]
    const float* t0   = (const float*)d_in[4];   // [A]
    float* out = (float*)d_out;                  // [A, NZ, NX]

    cudaFuncSetAttribute(das_main,
                         cudaFuncAttributeMaxDynamicSharedMemorySize,
                         SMEM_BYTES);

    das_init<<<INIT_GRID, 256>>>(rf, (float4*)out);
    das_main<<<GRID, THREADS, SMEM_BYTES>>>(d_tx, d_rx, apod, t0, out);
}

// round 17
// speedup vs baseline: 1.2430x; 1.0474x over previous
#include <cuda_runtime.h>
#include <cuda_fp16.h>
#include <cstdint>

#define A_N 4
#define E_N 128
#define S_N 3072
#define NPIX (512 * 256)              // 131072
#define THREADS 896                   // 28 warps
#define RPT 4
#define TILE_PX (THREADS * RPT)       // 3584
#define NTILE 37                      // 37*3584 = 132608 >= NPIX (guarded)
#define NGROUP 4
#define EPC (E_N / NGROUP)            // 32 elements per CTA
#define NPHASE EPC
#define GRID (NTILE * NGROUP)         // 148 = one CTA per SM
#define R4 (S_N / 4)                  // 768 uint4 per packed rf row
#define RF_U4 (A_N * R4)              // 3072 uint4 rf per buffer (48KB)
#define SC_U4 (TILE_PX / 4)           // 896 uint4 per scalar array (14KB)
#define BUF_U4 (RF_U4 + 2 * SC_U4)    // 4864 uint4 = 76KB per buffer
#define NBUF 2
#define SMEM_BYTES (NBUF * BUF_U4 * 16)   // 155648

#define ZERO_BLOCKS 512
#define PACK_BLOCKS (A_N * E_N * R4 / 256)   // 1536
#define INIT_GRID (ZERO_BLOCKS + PACK_BLOCKS)

// Pre-packed rf: [A][E][S] half2, entry i = (rf[i], rf[i+1]-rf[i])  (6MB)
__device__ half2 g_packed[A_N * E_N * S_N];

__device__ __forceinline__ void cp_async16(void* smem_ptr, const void* gptr) {
    unsigned s = (unsigned)__cvta_generic_to_shared(smem_ptr);
    asm volatile("cp.async.cg.shared.global [%0], [%1], 16;\n" :: "r"(s), "l"(gptr));
}

// ---- fused init: zero d_out + pack rf as (value, forward-difference) ----
__global__ void __launch_bounds__(256)
das_init(const float* __restrict__ rf, float4* __restrict__ out4)
{
    int b = blockIdx.x;
    if (b < ZERO_BLOCKS) {
        out4[b * 256 + threadIdx.x] = make_float4(0.f, 0.f, 0.f, 0.f);
        return;
    }
    int c = (b - ZERO_BLOCKS) * 256 + threadIdx.x;  // uint4 idx 0..A*E*R4-1
    int row = c / R4;                                // a*E_N + e
    int col = c - row * R4;
    const float* grow = rf + (size_t)row * S_N;
    float4 v  = ((const float4*)grow)[col];
    float  s4 = grow[min(col * 4 + 4, S_N - 1)];
    half2 q0 = __floats2half2_rn(v.x, v.y - v.x);
    half2 q1 = __floats2half2_rn(v.y, v.z - v.y);
    half2 q2 = __floats2half2_rn(v.z, v.w - v.z);
    half2 q3 = __floats2half2_rn(v.w, s4  - v.w);
    uint4 pk;
    pk.x = *(unsigned*)&q0; pk.y = *(unsigned*)&q1;
    pk.z = *(unsigned*)&q2; pk.w = *(unsigned*)&q3;
    ((uint4*)g_packed)[c] = pk;
}

__global__ void __launch_bounds__(THREADS, 1)
das_main(const float* __restrict__ d_tx, const float* __restrict__ d_rx,
         const float* __restrict__ apod, const float* __restrict__ t0,
         float* __restrict__ out)
{
    // buffer layout (uint4): [0,3072) rf | [3072,3968) drx | [3968,4864) apod
    extern __shared__ uint4 sm4[];
    const uint4* gp4 = (const uint4*)g_packed;

    const int tid   = threadIdx.x;
    const int group = blockIdx.x & (NGROUP - 1);
    const int tile  = blockIdx.x >> 2;
    const int ebase = group * EPC;
    const int pbase = tile * TILE_PX;
    const int p0    = pbase + tid;

    // Per-thread pixel validity (last tile overhangs NPIX)
    bool ok[RPT];
#pragma unroll
    for (int r = 0; r < RPT; r++) ok[r] = (p0 + r * THREADS) < NPIX;
    // scalar-tile copy validity: thread copies 16B at pbase + tid*4
    const bool okc = (pbase + tid * 4) < NPIX;

    auto stage = [&](int buf, int e) {
        uint4* dst = sm4 + buf * BUF_U4;
#pragma unroll
        for (int k = 0; k < (RF_U4 + THREADS - 1) / THREADS; k++) {  // 4 iters
            int c = tid + k * THREADS;
            if (c < RF_U4) {
                int a   = c / R4;
                int col = c - a * R4;
                cp_async16(&dst[c], &gp4[((size_t)a * E_N + e) * R4 + col]);
            }
        }
        if (okc) {
            const uint4* gdrx = (const uint4*)(d_rx + (size_t)e * NPIX + pbase);
            const uint4* gap  = (const uint4*)(apod + (size_t)e * NPIX + pbase);
            cp_async16(&dst[RF_U4 + tid],         &gdrx[tid]);
            cp_async16(&dst[RF_U4 + SC_U4 + tid], &gap[tid]);
        }
        asm volatile("cp.async.commit_group;\n" ::);
    };

    float dtx[A_N][RPT];
    float acc[A_N][RPT];
#pragma unroll
    for (int a = 0; a < A_N; a++) {
        float t0a = t0[a];
#pragma unroll
        for (int r = 0; r < RPT; r++) {
            dtx[a][r] = ok[r] ? (d_tx[(size_t)a * NPIX + p0 + r * THREADS] - t0a)
                              : 0.0f;
            acc[a][r] = 0.0f;
        }
    }

    stage(0, ebase);                         // prologue

    for (int ph = 0; ph < NPHASE; ph++) {
        if (ph + 1 < NPHASE) {
            stage((ph + 1) & 1, ebase + ph + 1);
            asm volatile("cp.async.wait_group 1;\n" ::);  // buf ph complete
        } else {
            asm volatile("cp.async.wait_group 0;\n" ::);
        }
        __syncthreads();                     // buf ph visible

        const uint4* bufb = sm4 + (ph & 1) * BUF_U4;
        const half2* rfp  = (const half2*)bufb;
        const float* sdrx = (const float*)(bufb + RF_U4);
        const float* sap  = (const float*)(bufb + RF_U4 + SC_U4);

#pragma unroll
        for (int r = 0; r < RPT; r++) {
            float drx = sdrx[tid + r * THREADS];   // coalesced LDS (29cyc)
            float ap  = sap [tid + r * THREADS];
            // invalid pixels: force index 0 (garbage math, result discarded)
            if (!ok[r]) { drx = 0.0f; ap = 0.0f; }
#pragma unroll
            for (int a = 0; a < A_N; a++) {
                const half2* row = rfp + a * S_N;
                float delay = dtx[a][r] + drx;
                float f  = floorf(delay);
                float w  = delay - f;
                int   i0 = (int)f;           // in-range by data (0 for dead lanes)
                half2 pr = row[i0];          // 1 LDS.32: (v0, dv)
                float v0 = __low2float(pr);
                float dv = __high2float(pr);
                float s  = fmaf(w, dv, v0);
                acc[a][r] = fmaf(s, ap, acc[a][r]);
            }
        }
        __syncthreads();                     // reads done before buf reuse
    }

    // Atomic epilogue (guarded)
#pragma unroll
    for (int a = 0; a < A_N; a++)
#pragma unroll
        for (int r = 0; r < RPT; r++)
            if (ok[r])
                atomicAdd(&out[(size_t)a * NPIX + p0 + r * THREADS], acc[a][r]);
}

extern "C" void kernel_launch(void* const* d_in, const int* in_sizes, int n_in,
                              void* d_out, int out_size)
{
    const float* d_tx = (const float*)d_in[0];   // [A, NZ, NX]
    const float* d_rx = (const float*)d_in[1];   // [E, NZ, NX]
    const float* apod = (const float*)d_in[2];   // [E, NZ, NX]
    const float* rf   = (const float*)d_in[3];   // [A, E, S]
    const float* t0   = (const float*)d_in[4];   // [A]
    float* out = (float*)d_out;                  // [A, NZ, NX]

    cudaFuncSetAttribute(das_main,
                         cudaFuncAttributeMaxDynamicSharedMemorySize,
                         SMEM_BYTES);

    das_init<<<INIT_GRID, 256>>>(rf, (float4*)out);
    das_main<<<GRID, THREADS, SMEM_BYTES>>>(d_tx, d_rx, apod, t0, out);
}